// round 12
// baseline (speedup 1.0000x reference)
#include <cuda_runtime.h>
#include <cuda_fp16.h>
#include <stdint.h>

#define NN 100000
#define EE 1600000
// dims: IN=64, HID=128, OUT=64

// ---------------- device scratch (no allocation allowed) ----------------
__device__ int g_idx64;
__device__ __align__(16) int    g_deg[NN];
__device__ __align__(16) int    g_rowstart[NN + 1];
__device__ __align__(16) int    g_cur[NN];
__device__ __align__(16) int    g_adj[EE];
__device__ __align__(16) int    g_blocksum[128];
__device__ __align__(16) int    g_blockoff[128];
// GEMM operands pre-split to fp16 hi/lo
__device__ __align__(16) __half g_fh [(size_t)NN * 64];
__device__ __align__(16) __half g_fl [(size_t)NN * 64];
__device__ __align__(16) __half g_h1h[(size_t)NN * 64];
__device__ __align__(16) __half g_h1l[(size_t)NN * 64];
__device__ __align__(16) __half g_x1h[(size_t)NN * 128];
__device__ __align__(16) __half g_x1l[(size_t)NN * 128];
__device__ __align__(16) __half g_h2h[(size_t)NN * 128];
__device__ __align__(16) __half g_h2l[(size_t)NN * 128];
__device__ __align__(16) __half g_x2h[(size_t)NN * 128];
__device__ __align__(16) __half g_x2l[(size_t)NN * 128];
// weight arenas, pre-split + pre-transposed to [col][k]
// offsets: L1=0 (128x128), L2=16384 (256x128), L3=49152 (128x128), L4=65536 (128x64)
__device__ __align__(16) __half g_wh[73728];
__device__ __align__(16) __half g_wl[73728];

// ---------------- small helpers ----------------
__device__ __forceinline__ void split_h(float x, __half& hi, __half& lo) {
    hi = __float2half_rn(x);
    lo = __float2half_rn(x - __half2float(hi));
}

// ---------------- init: index dtype detection + degree zero ----------------
__global__ void k_init(const void* srcp) {
    int n = blockIdx.x * blockDim.x + threadIdx.x;
    if (n < NN) g_deg[n] = 0;
    if (blockIdx.x == 0 && threadIdx.x < 32) {
        const long long* s = (const long long*)srcp;
        long long v = s[threadIdx.x];
        int ok = (v >= 0 && v < NN) ? 1 : 0;
        ok = __all_sync(~0u, ok);
        if (threadIdx.x == 0) g_idx64 = ok;
    }
}

// features (fp32) -> hi/lo fp16
__global__ void k_cvt_f(const float2* __restrict__ f) {
    int i = blockIdx.x * blockDim.x + threadIdx.x;
    if (i >= NN * 32) return;
    float2 v = f[i];
    __half h0, l0, h1, l1;
    split_h(v.x, h0, l0);
    split_h(v.y, h1, l1);
    *(__half2*)&g_fh[(size_t)i * 2] = __halves2half2(h0, h1);
    *(__half2*)&g_fl[(size_t)i * 2] = __halves2half2(l0, l1);
}

// all weights: split + transpose into [col][k] arena
__global__ void k_prep_all(const float* __restrict__ Ws1, const float* __restrict__ Wn1,
                           const float* __restrict__ Ws2, const float* __restrict__ Wn2,
                           const float* __restrict__ Wm1, const float* __restrict__ Wm2) {
    int i = blockIdx.x * blockDim.x + threadIdx.x;
    if (i >= 73728) return;
    float v;
    if (i < 16384) {                       // L1: K=128, K0=64, NCOL=128
        int col = i / 128, k = i % 128;
        v = (k < 64) ? Ws1[k * 128 + col] : Wn1[(k - 64) * 128 + col];
    } else if (i < 49152) {                // L2: K=256, K0=128, NCOL=128
        int j = i - 16384;
        int col = j / 256, k = j % 256;
        v = (k < 128) ? Ws2[k * 128 + col] : Wn2[(k - 128) * 128 + col];
    } else if (i < 65536) {                // L3: K=128, NCOL=128
        int j = i - 49152;
        int col = j / 128, k = j % 128;
        v = Wm1[k * 128 + col];
    } else {                               // L4: K=128, NCOL=64
        int j = i - 65536;
        int col = j / 128, k = j % 128;
        v = Wm2[k * 64 + col];
    }
    __half h, l;
    split_h(v, h, l);
    g_wh[i] = h;
    g_wl[i] = l;
}

__device__ __forceinline__ int load_idx(const void* p, int e) {
    return g_idx64 ? (int)((const long long*)p)[e] : ((const int*)p)[e];
}

// ---------------- CSR build: count, 3-phase scan, fill ----------------
__global__ void k_count(const void* dstp) {
    int e = blockIdx.x * blockDim.x + threadIdx.x;
    if (e >= EE) return;
    atomicAdd(&g_deg[load_idx(dstp, e)], 1);
}

__global__ __launch_bounds__(1024) void k_scan1() {
    __shared__ int ws[32];
    int t = threadIdx.x, lane = t & 31, wid = t >> 5;
    int idx = blockIdx.x * 1024 + t;
    int s = (idx < NN) ? g_deg[idx] : 0;
#pragma unroll
    for (int o = 16; o > 0; o >>= 1) s += __shfl_down_sync(~0u, s, o);
    if (lane == 0) ws[wid] = s;
    __syncthreads();
    if (wid == 0) {
        int x = ws[lane];
#pragma unroll
        for (int o = 16; o > 0; o >>= 1) x += __shfl_down_sync(~0u, x, o);
        if (lane == 0) g_blocksum[blockIdx.x] = x;
    }
}

__global__ __launch_bounds__(128) void k_scan2(int nb) {
    __shared__ int ws[4];
    int t = threadIdx.x, lane = t & 31, wid = t >> 5;
    int v = (t < nb) ? g_blocksum[t] : 0;
    int inc = v;
#pragma unroll
    for (int o = 1; o < 32; o <<= 1) {
        int n = __shfl_up_sync(~0u, inc, o);
        if (lane >= o) inc += n;
    }
    if (lane == 31) ws[wid] = inc;
    __syncthreads();
    int add = 0;
    for (int i = 0; i < wid; i++) add += ws[i];
    if (t < nb) g_blockoff[t] = inc - v + add;  // exclusive
}

__global__ __launch_bounds__(1024) void k_scan3() {
    __shared__ int ws[32];
    int t = threadIdx.x, lane = t & 31, wid = t >> 5;
    int idx = blockIdx.x * 1024 + t;
    int v = (idx < NN) ? g_deg[idx] : 0;
    int inc = v;
#pragma unroll
    for (int o = 1; o < 32; o <<= 1) {
        int n = __shfl_up_sync(~0u, inc, o);
        if (lane >= o) inc += n;
    }
    if (lane == 31) ws[wid] = inc;
    __syncthreads();
    if (wid == 0) {
        int x = ws[lane];
#pragma unroll
        for (int o = 1; o < 32; o <<= 1) {
            int n = __shfl_up_sync(~0u, x, o);
            if (lane >= o) x += n;
        }
        ws[lane] = x;
    }
    __syncthreads();
    int exc = inc - v + (wid > 0 ? ws[wid - 1] : 0) + g_blockoff[blockIdx.x];
    if (idx < NN) {
        g_rowstart[idx] = exc;
        g_cur[idx] = exc;
    }
    if (idx == NN - 1) g_rowstart[NN] = EE;
}

__global__ void k_fill(const void* srcp, const void* dstp) {
    int e = blockIdx.x * blockDim.x + threadIdx.x;
    if (e >= EE) return;
    int s = load_idx(srcp, e);
    int d = load_idx(dstp, e);
    int pos = atomicAdd(&g_cur[d], 1);
    g_adj[pos] = s;
}

// ---------------- fp16 gather aggregation -> hi/lo split output ----------
template <int LANES>
__global__ void k_gather_h(const uint4* __restrict__ x,
                           __half* __restrict__ hh, __half* __restrict__ hl) {
    int tid = blockIdx.x * blockDim.x + threadIdx.x;
    int node = tid / LANES;
    int l = tid % LANES;
    if (node >= NN) return;
    int i = g_rowstart[node];
    const int end = g_rowstart[node + 1];
    const int deg = end - i;
    float acc[8];
#pragma unroll
    for (int j = 0; j < 8; j++) acc[j] = 0.f;
#pragma unroll 1
    for (; i + 4 <= end; i += 4) {
        int n0 = g_adj[i], n1 = g_adj[i + 1], n2 = g_adj[i + 2], n3 = g_adj[i + 3];
        uint4 v0 = x[(size_t)n0 * LANES + l];
        uint4 v1 = x[(size_t)n1 * LANES + l];
        uint4 v2 = x[(size_t)n2 * LANES + l];
        uint4 v3 = x[(size_t)n3 * LANES + l];
        const uint32_t* vs[4] = {&v0.x, &v1.x, &v2.x, &v3.x};
#pragma unroll
        for (int q = 0; q < 4; q++) {
#pragma unroll
            for (int j = 0; j < 4; j++) {
                float2 f = __half22float2(*(const __half2*)&vs[q][j]);
                acc[2 * j] += f.x;
                acc[2 * j + 1] += f.y;
            }
        }
    }
    for (; i < end; i++) {
        uint4 v = x[(size_t)g_adj[i] * LANES + l];
        const uint32_t* vp = &v.x;
#pragma unroll
        for (int j = 0; j < 4; j++) {
            float2 f = __half22float2(*(const __half2*)&vp[j]);
            acc[2 * j] += f.x;
            acc[2 * j + 1] += f.y;
        }
    }
    float inv = 1.f / (float)max(deg, 1);
    __half hv[8], lv[8];
#pragma unroll
    for (int j = 0; j < 8; j++) split_h(acc[j] * inv, hv[j], lv[j]);
    size_t o = ((size_t)node * LANES + l) * 8;
    *(uint4*)&hh[o] = *(uint4*)hv;
    *(uint4*)&hl[o] = *(uint4*)lv;
}

// ---------------- FP16x2-split tensor-core dense layers ----------------
__device__ __forceinline__ void mma_fp16(float c[4], uint32_t a0, uint32_t a1,
                                         uint32_t a2, uint32_t a3,
                                         uint32_t b0, uint32_t b1) {
    asm volatile(
        "mma.sync.aligned.m16n8k16.row.col.f32.f16.f16.f32 "
        "{%0,%1,%2,%3}, {%4,%5,%6,%7}, {%8,%9}, {%0,%1,%2,%3};"
        : "+f"(c[0]), "+f"(c[1]), "+f"(c[2]), "+f"(c[3])
        : "r"(a0), "r"(a1), "r"(a2), "r"(a3), "r"(b0), "r"(b1));
}

#define HSTR 40  // fragment LDS bank = (4g+t) mod 32, all lanes distinct

// ---- standalone layer kernel (layers 1 & 2): out split hi/lo fp16 ----
template <int K, int K0>
__global__ __launch_bounds__(256, 2) void k_gemm_fp16s(
    const __half* __restrict__ Ah0, const __half* __restrict__ Al0,
    const __half* __restrict__ Ah1, const __half* __restrict__ Al1,
    const __half* __restrict__ Bh, const __half* __restrict__ Bl,
    const float* __restrict__ bias,
    __half* __restrict__ outh, __half* __restrict__ outl) {
    constexpr int NCOL = 128;
    constexpr int MT = 2, NT = 8, NTG = 4;

    __shared__ __half As_hi[128 * HSTR];
    __shared__ __half As_lo[128 * HSTR];
    __shared__ __half Bs_hi[NCOL * HSTR];   // [col][k]
    __shared__ __half Bs_lo[NCOL * HSTR];

    const int tid = threadIdx.x;
    const int w = tid >> 5;
    const int lane = tid & 31;
    const int g = lane >> 2;
    const int t = lane & 3;
    const int rowBase = blockIdx.x * 128;
    const int rbase = (w & 3) * 32;
    const int cbase = (w >> 2) * 64;

    float acc[MT][NT][4];
#pragma unroll
    for (int mt = 0; mt < MT; mt++)
#pragma unroll
        for (int nt = 0; nt < NT; nt++)
#pragma unroll
            for (int i = 0; i < 4; i++) acc[mt][nt][i] = 0.f;

    const int pr0 = tid >> 2, pq0 = tid & 3;
    const int pr1 = (tid + 256) >> 2, pq1 = tid & 3;
    uint4 pah[2], pal[2];
    auto loadA = [&](int kc) {
        const __half *sAh, *sAl;
        int stride;
        if (kc < K0) { sAh = Ah0; sAl = Al0; stride = K0; }
        else { sAh = Ah1; sAl = Al1; stride = K - K0; kc -= K0; }
        int gr0 = rowBase + pr0, gr1 = rowBase + pr1;
        pah[0] = pal[0] = pah[1] = pal[1] = make_uint4(0, 0, 0, 0);
        if (gr0 < NN) {
            pah[0] = *(const uint4*)(sAh + (size_t)gr0 * stride + kc + pq0 * 8);
            pal[0] = *(const uint4*)(sAl + (size_t)gr0 * stride + kc + pq0 * 8);
        }
        if (gr1 < NN) {
            pah[1] = *(const uint4*)(sAh + (size_t)gr1 * stride + kc + pq1 * 8);
            pal[1] = *(const uint4*)(sAl + (size_t)gr1 * stride + kc + pq1 * 8);
        }
    };

    loadA(0);
    for (int kc = 0; kc < K; kc += 32) {
        *(uint4*)&As_hi[pr0 * HSTR + pq0 * 8] = pah[0];
        *(uint4*)&As_lo[pr0 * HSTR + pq0 * 8] = pal[0];
        *(uint4*)&As_hi[pr1 * HSTR + pq1 * 8] = pah[1];
        *(uint4*)&As_lo[pr1 * HSTR + pq1 * 8] = pal[1];
#pragma unroll
        for (int x = tid; x < NCOL * 4; x += 256) {
            int c = x >> 2, q = x & 3;
            *(uint4*)&Bs_hi[c * HSTR + q * 8] =
                *(const uint4*)(Bh + (size_t)c * K + kc + q * 8);
            *(uint4*)&Bs_lo[c * HSTR + q * 8] =
                *(const uint4*)(Bl + (size_t)c * K + kc + q * 8);
        }
        __syncthreads();

        if (kc + 32 < K) loadA(kc + 32);

#pragma unroll
        for (int k16 = 0; k16 < 2; k16++) {
            const int kk = k16 * 16;
            uint32_t ah[MT][4], al[MT][4];
#pragma unroll
            for (int mt = 0; mt < MT; mt++) {
                int r0 = rbase + mt * 16 + g;
                const __half* ph = As_hi + kk + 2 * t;
                const __half* pl = As_lo + kk + 2 * t;
                ah[mt][0] = *(const uint32_t*)(ph + r0 * HSTR);
                ah[mt][1] = *(const uint32_t*)(ph + (r0 + 8) * HSTR);
                ah[mt][2] = *(const uint32_t*)(ph + r0 * HSTR + 8);
                ah[mt][3] = *(const uint32_t*)(ph + (r0 + 8) * HSTR + 8);
                al[mt][0] = *(const uint32_t*)(pl + r0 * HSTR);
                al[mt][1] = *(const uint32_t*)(pl + (r0 + 8) * HSTR);
                al[mt][2] = *(const uint32_t*)(pl + r0 * HSTR + 8);
                al[mt][3] = *(const uint32_t*)(pl + (r0 + 8) * HSTR + 8);
            }
#pragma unroll
            for (int ng = 0; ng < NT / NTG; ng++) {
                uint32_t bh[NTG][2], bl[NTG][2];
#pragma unroll
                for (int j = 0; j < NTG; j++) {
                    int col = cbase + (ng * NTG + j) * 8 + g;
                    const __half* ph = Bs_hi + col * HSTR + kk + 2 * t;
                    const __half* pl = Bs_lo + col * HSTR + kk + 2 * t;
                    bh[j][0] = *(const uint32_t*)(ph);
                    bh[j][1] = *(const uint32_t*)(ph + 8);
                    bl[j][0] = *(const uint32_t*)(pl);
                    bl[j][1] = *(const uint32_t*)(pl + 8);
                }
#pragma unroll
                for (int mt = 0; mt < MT; mt++) {
#pragma unroll
                    for (int j = 0; j < NTG; j++) {
                        float* a = acc[mt][ng * NTG + j];
                        mma_fp16(a, ah[mt][0], ah[mt][1], ah[mt][2], ah[mt][3],
                                 bh[j][0], bh[j][1]);
                        mma_fp16(a, ah[mt][0], ah[mt][1], ah[mt][2], ah[mt][3],
                                 bl[j][0], bl[j][1]);
                        mma_fp16(a, al[mt][0], al[mt][1], al[mt][2], al[mt][3],
                                 bh[j][0], bh[j][1]);
                    }
                }
            }
        }
        __syncthreads();
    }

    // epilogue: bias + relu, write hi/lo fp16
#pragma unroll
    for (int mt = 0; mt < MT; mt++) {
#pragma unroll
        for (int nt = 0; nt < NT; nt++) {
            int col = cbase + nt * 8 + t * 2;
            float b0 = bias[col], b1 = bias[col + 1];
#pragma unroll
            for (int half = 0; half < 2; half++) {
                int gr = rowBase + rbase + mt * 16 + g + half * 8;
                if (gr < NN) {
                    float v0 = fmaxf(acc[mt][nt][half * 2 + 0] + b0, 0.f);
                    float v1 = fmaxf(acc[mt][nt][half * 2 + 1] + b1, 0.f);
                    __half h0, l0, h1, l1;
                    split_h(v0, h0, l0);
                    split_h(v1, h1, l1);
                    *(__half2*)(outh + (size_t)gr * 128 + col) = __halves2half2(h0, h1);
                    *(__half2*)(outl + (size_t)gr * 128 + col) = __halves2half2(l0, l1);
                }
            }
        }
    }
}

// ---- fused MLP head: x3 = relu(x2 @ Wm1 + bm1); out = x3 @ Wm2 + bm2 ----
// Phase 1: standard K=128 mainloop, acc1 holds x3 (pre-bias).
// Phase 2: x3 staged chunk-wise from registers into As (bias+relu+split
// in-flight), 64-col GEMM against Wm2. x3 never touches global memory.
__global__ __launch_bounds__(256, 2) void k_gemm_mlp(
    const __half* __restrict__ Ah, const __half* __restrict__ Al,
    const __half* __restrict__ B1h, const __half* __restrict__ B1l,
    const float* __restrict__ bm1,
    const __half* __restrict__ B2h, const __half* __restrict__ B2l,
    const float* __restrict__ bm2, float* __restrict__ out) {
    __shared__ __half As_hi[128 * HSTR];
    __shared__ __half As_lo[128 * HSTR];
    __shared__ __half Bs_hi[128 * HSTR];
    __shared__ __half Bs_lo[128 * HSTR];

    const int tid = threadIdx.x;
    const int w = tid >> 5;
    const int lane = tid & 31;
    const int g = lane >> 2;
    const int t = lane & 3;
    const int rowBase = blockIdx.x * 128;
    const int rbase = (w & 3) * 32;
    const int cbase = (w >> 2) * 64;

    float acc1[2][8][4];
#pragma unroll
    for (int mt = 0; mt < 2; mt++)
#pragma unroll
        for (int nt = 0; nt < 8; nt++)
#pragma unroll
            for (int i = 0; i < 4; i++) acc1[mt][nt][i] = 0.f;

    const int pr0 = tid >> 2, pq0 = tid & 3;
    const int pr1 = (tid + 256) >> 2, pq1 = tid & 3;
    uint4 pah[2], pal[2];
    auto loadA = [&](int kc) {
        int gr0 = rowBase + pr0, gr1 = rowBase + pr1;
        pah[0] = pal[0] = pah[1] = pal[1] = make_uint4(0, 0, 0, 0);
        if (gr0 < NN) {
            pah[0] = *(const uint4*)(Ah + (size_t)gr0 * 128 + kc + pq0 * 8);
            pal[0] = *(const uint4*)(Al + (size_t)gr0 * 128 + kc + pq0 * 8);
        }
        if (gr1 < NN) {
            pah[1] = *(const uint4*)(Ah + (size_t)gr1 * 128 + kc + pq1 * 8);
            pal[1] = *(const uint4*)(Al + (size_t)gr1 * 128 + kc + pq1 * 8);
        }
    };

    // ---- phase 1 ----
    loadA(0);
    for (int kc = 0; kc < 128; kc += 32) {
        *(uint4*)&As_hi[pr0 * HSTR + pq0 * 8] = pah[0];
        *(uint4*)&As_lo[pr0 * HSTR + pq0 * 8] = pal[0];
        *(uint4*)&As_hi[pr1 * HSTR + pq1 * 8] = pah[1];
        *(uint4*)&As_lo[pr1 * HSTR + pq1 * 8] = pal[1];
#pragma unroll
        for (int x = tid; x < 128 * 4; x += 256) {
            int c = x >> 2, q = x & 3;
            *(uint4*)&Bs_hi[c * HSTR + q * 8] =
                *(const uint4*)(B1h + (size_t)c * 128 + kc + q * 8);
            *(uint4*)&Bs_lo[c * HSTR + q * 8] =
                *(const uint4*)(B1l + (size_t)c * 128 + kc + q * 8);
        }
        __syncthreads();
        if (kc + 32 < 128) loadA(kc + 32);
#pragma unroll
        for (int k16 = 0; k16 < 2; k16++) {
            const int kk = k16 * 16;
            uint32_t ah[2][4], al[2][4];
#pragma unroll
            for (int mt = 0; mt < 2; mt++) {
                int r0 = rbase + mt * 16 + g;
                const __half* ph = As_hi + kk + 2 * t;
                const __half* pl = As_lo + kk + 2 * t;
                ah[mt][0] = *(const uint32_t*)(ph + r0 * HSTR);
                ah[mt][1] = *(const uint32_t*)(ph + (r0 + 8) * HSTR);
                ah[mt][2] = *(const uint32_t*)(ph + r0 * HSTR + 8);
                ah[mt][3] = *(const uint32_t*)(ph + (r0 + 8) * HSTR + 8);
                al[mt][0] = *(const uint32_t*)(pl + r0 * HSTR);
                al[mt][1] = *(const uint32_t*)(pl + (r0 + 8) * HSTR);
                al[mt][2] = *(const uint32_t*)(pl + r0 * HSTR + 8);
                al[mt][3] = *(const uint32_t*)(pl + (r0 + 8) * HSTR + 8);
            }
#pragma unroll
            for (int ng = 0; ng < 2; ng++) {
                uint32_t bh[4][2], bl[4][2];
#pragma unroll
                for (int j = 0; j < 4; j++) {
                    int col = cbase + (ng * 4 + j) * 8 + g;
                    const __half* ph = Bs_hi + col * HSTR + kk + 2 * t;
                    const __half* pl = Bs_lo + col * HSTR + kk + 2 * t;
                    bh[j][0] = *(const uint32_t*)(ph);
                    bh[j][1] = *(const uint32_t*)(ph + 8);
                    bl[j][0] = *(const uint32_t*)(pl);
                    bl[j][1] = *(const uint32_t*)(pl + 8);
                }
#pragma unroll
                for (int mt = 0; mt < 2; mt++) {
#pragma unroll
                    for (int j = 0; j < 4; j++) {
                        float* a = acc1[mt][ng * 4 + j];
                        mma_fp16(a, ah[mt][0], ah[mt][1], ah[mt][2], ah[mt][3],
                                 bh[j][0], bh[j][1]);
                        mma_fp16(a, ah[mt][0], ah[mt][1], ah[mt][2], ah[mt][3],
                                 bl[j][0], bl[j][1]);
                        mma_fp16(a, al[mt][0], al[mt][1], al[mt][2], al[mt][3],
                                 bh[j][0], bh[j][1]);
                    }
                }
            }
        }
        __syncthreads();
    }

    // ---- phase 2: out = x3 @ Wm2 + bm2, x3 staged from acc1 ----
    float acc2[8][4];
#pragma unroll
    for (int nt = 0; nt < 8; nt++)
#pragma unroll
        for (int i = 0; i < 4; i++) acc2[nt][i] = 0.f;

    const int rbase2 = w * 16;  // 64-col warp mapping: 8 warps x 16 rows

    for (int kc = 0; kc < 128; kc += 32) {
        // stage x3 chunk from registers (bias + relu + split in-flight)
        if (kc >= cbase && kc < cbase + 64) {
            int nt0 = (kc - cbase) >> 3;  // 0 or 4
#pragma unroll
            for (int mt = 0; mt < 2; mt++) {
#pragma unroll
                for (int j = 0; j < 4; j++) {
                    int nt = nt0 + j;
                    int col = cbase + nt * 8 + t * 2;
                    float b0 = bm1[col], b1 = bm1[col + 1];
                    int kk2 = col - kc;  // 0..30, even
#pragma unroll
                    for (int half = 0; half < 2; half++) {
                        int r = rbase + mt * 16 + g + half * 8;
                        float v0 = fmaxf(acc1[mt][nt][half * 2 + 0] + b0, 0.f);
                        float v1 = fmaxf(acc1[mt][nt][half * 2 + 1] + b1, 0.f);
                        __half h0, l0, h1, l1;
                        split_h(v0, h0, l0);
                        split_h(v1, h1, l1);
                        *(__half2*)&As_hi[r * HSTR + kk2] = __halves2half2(h0, h1);
                        *(__half2*)&As_lo[r * HSTR + kk2] = __halves2half2(l0, l1);
                    }
                }
            }
        }
        // stage Wm2 chunk: 64 cols x 4 uint4 = 256 units, 1 per thread
        {
            int c = tid >> 2, q = tid & 3;
            *(uint4*)&Bs_hi[c * HSTR + q * 8] =
                *(const uint4*)(B2h + (size_t)c * 128 + kc + q * 8);
            *(uint4*)&Bs_lo[c * HSTR + q * 8] =
                *(const uint4*)(B2l + (size_t)c * 128 + kc + q * 8);
        }
        __syncthreads();

#pragma unroll
        for (int k16 = 0; k16 < 2; k16++) {
            const int kk = k16 * 16;
            int r0 = rbase2 + g;
            const __half* ph = As_hi + kk + 2 * t;
            const __half* pl = As_lo + kk + 2 * t;
            uint32_t ah[4], al[4];
            ah[0] = *(const uint32_t*)(ph + r0 * HSTR);
            ah[1] = *(const uint32_t*)(ph + (r0 + 8) * HSTR);
            ah[2] = *(const uint32_t*)(ph + r0 * HSTR + 8);
            ah[3] = *(const uint32_t*)(ph + (r0 + 8) * HSTR + 8);
            al[0] = *(const uint32_t*)(pl + r0 * HSTR);
            al[1] = *(const uint32_t*)(pl + (r0 + 8) * HSTR);
            al[2] = *(const uint32_t*)(pl + r0 * HSTR + 8);
            al[3] = *(const uint32_t*)(pl + (r0 + 8) * HSTR + 8);
#pragma unroll
            for (int ng = 0; ng < 2; ng++) {
                uint32_t bh[4][2], bl[4][2];
#pragma unroll
                for (int j = 0; j < 4; j++) {
                    int col = (ng * 4 + j) * 8 + g;
                    const __half* qh = Bs_hi + col * HSTR + kk + 2 * t;
                    const __half* ql = Bs_lo + col * HSTR + kk + 2 * t;
                    bh[j][0] = *(const uint32_t*)(qh);
                    bh[j][1] = *(const uint32_t*)(qh + 8);
                    bl[j][0] = *(const uint32_t*)(ql);
                    bl[j][1] = *(const uint32_t*)(ql + 8);
                }
#pragma unroll
                for (int j = 0; j < 4; j++) {
                    float* a = acc2[ng * 4 + j];
                    mma_fp16(a, ah[0], ah[1], ah[2], ah[3], bh[j][0], bh[j][1]);
                    mma_fp16(a, ah[0], ah[1], ah[2], ah[3], bl[j][0], bl[j][1]);
                    mma_fp16(a, al[0], al[1], al[2], al[3], bh[j][0], bh[j][1]);
                }
            }
        }
        __syncthreads();
    }

    // final epilogue: fp32 output, 64 cols
#pragma unroll
    for (int nt = 0; nt < 8; nt++) {
        int col = nt * 8 + t * 2;
        float b0 = bm2[col], b1 = bm2[col + 1];
#pragma unroll
        for (int half = 0; half < 2; half++) {
            int gr = rowBase + rbase2 + g + half * 8;
            if (gr < NN) {
                float v0 = acc2[nt][half * 2 + 0] + b0;
                float v1 = acc2[nt][half * 2 + 1] + b1;
                *(float2*)(out + (size_t)gr * 64 + col) = make_float2(v0, v1);
            }
        }
    }
}

// ---------------- launch ----------------
extern "C" void kernel_launch(void* const* d_in, const int* in_sizes, int n_in,
                              void* d_out, int out_size) {
    const float* features = (const float*)d_in[0];
    const float* Wn1 = (const float*)d_in[1];
    const float* Ws1 = (const float*)d_in[2];
    const float* b1  = (const float*)d_in[3];
    const float* Wn2 = (const float*)d_in[4];
    const float* Ws2 = (const float*)d_in[5];
    const float* b2  = (const float*)d_in[6];
    const float* Wm1 = (const float*)d_in[7];
    const float* bm1 = (const float*)d_in[8];
    const float* Wm2 = (const float*)d_in[9];
    const float* bm2 = (const float*)d_in[10];
    const void*  src = d_in[11];
    const void*  dst = d_in[12];
    float* out = (float*)d_out;

    __half *p_fh, *p_fl, *p_h1h, *p_h1l, *p_x1h, *p_x1l;
    __half *p_h2h, *p_h2l, *p_x2h, *p_x2l, *p_wh, *p_wl;
    cudaGetSymbolAddress((void**)&p_fh, g_fh);
    cudaGetSymbolAddress((void**)&p_fl, g_fl);
    cudaGetSymbolAddress((void**)&p_h1h, g_h1h);
    cudaGetSymbolAddress((void**)&p_h1l, g_h1l);
    cudaGetSymbolAddress((void**)&p_x1h, g_x1h);
    cudaGetSymbolAddress((void**)&p_x1l, g_x1l);
    cudaGetSymbolAddress((void**)&p_h2h, g_h2h);
    cudaGetSymbolAddress((void**)&p_h2l, g_h2l);
    cudaGetSymbolAddress((void**)&p_x2h, g_x2h);
    cudaGetSymbolAddress((void**)&p_x2l, g_x2l);
    cudaGetSymbolAddress((void**)&p_wh, g_wh);
    cudaGetSymbolAddress((void**)&p_wl, g_wl);

    const int GEMM_BLOCKS = (NN + 127) / 128;  // 782
    const int EB = (EE + 255) / 256;
    const int NB = (NN + 1023) / 1024;

    // CSR build first (ncu -s 5 -c 1 lands on k_fill)
    k_init<<<(NN + 255) / 256, 256>>>(src);
    k_count<<<EB, 256>>>(dst);
    k_scan1<<<NB, 1024>>>();
    k_scan2<<<1, 128>>>(NB);
    k_scan3<<<NB, 1024>>>();
    k_fill<<<EB, 256>>>(src, dst);

    // operand prep
    k_cvt_f<<<(NN * 32 + 255) / 256, 256>>>((const float2*)features);
    k_prep_all<<<(73728 + 255) / 256, 256>>>(Ws1, Wn1, Ws2, Wn2, Wm1, Wm2);

    // layer 1
    k_gather_h<8><<<(NN * 8 + 255) / 256, 256>>>((const uint4*)p_fh, p_h1h, p_h1l);
    k_gemm_fp16s<128, 64><<<GEMM_BLOCKS, 256>>>(
        p_fh, p_fl, p_h1h, p_h1l, p_wh, p_wl, b1, p_x1h, p_x1l);

    // layer 2
    k_gather_h<16><<<(NN * 16 + 255) / 256, 256>>>((const uint4*)p_x1h, p_h2h, p_h2l);
    k_gemm_fp16s<256, 128><<<GEMM_BLOCKS, 256>>>(
        p_x1h, p_x1l, p_h2h, p_h2l, p_wh + 16384, p_wl + 16384, b2, p_x2h, p_x2l);

    // fused MLP head (x3 never hits global memory)
    k_gemm_mlp<<<GEMM_BLOCKS, 256>>>(
        p_x2h, p_x2l, p_wh + 49152, p_wl + 49152, bm1,
        p_wh + 65536, p_wl + 65536, bm2, out);
}

// round 14
// speedup vs baseline: 1.0786x; 1.0786x over previous
#include <cuda_runtime.h>
#include <cuda_fp16.h>
#include <stdint.h>

#define NN 100000
#define EE 1600000
// dims: IN=64, HID=128, OUT=64

// ---------------- device scratch (no allocation allowed) ----------------
__device__ int g_idx64;
__device__ __align__(16) int    g_deg[NN];
__device__ __align__(16) int    g_rowstart[NN + 1];
__device__ __align__(16) int    g_cur[NN];
__device__ __align__(16) int    g_adj[EE];
__device__ __align__(16) int    g_blocksum[128];
__device__ __align__(16) int    g_blockoff[128];
// GEMM operands pre-split to fp16 hi/lo
__device__ __align__(16) __half g_fh [(size_t)NN * 64];
__device__ __align__(16) __half g_fl [(size_t)NN * 64];
__device__ __align__(16) __half g_h1h[(size_t)NN * 64];
__device__ __align__(16) __half g_h1l[(size_t)NN * 64];
__device__ __align__(16) __half g_x1h[(size_t)NN * 128];
__device__ __align__(16) __half g_x1l[(size_t)NN * 128];
__device__ __align__(16) __half g_h2h[(size_t)NN * 128];
__device__ __align__(16) __half g_h2l[(size_t)NN * 128];
__device__ __align__(16) __half g_x2h[(size_t)NN * 128];
__device__ __align__(16) __half g_x2l[(size_t)NN * 128];
__device__ __align__(16) __half g_x3h[(size_t)NN * 128];
__device__ __align__(16) __half g_x3l[(size_t)NN * 128];
// weight arenas, pre-split + pre-transposed to [col][k]
// offsets: L1=0 (128x128), L2=16384 (256x128), L3=49152 (128x128), L4=65536 (128x64)
__device__ __align__(16) __half g_wh[73728];
__device__ __align__(16) __half g_wl[73728];

// ---------------- small helpers ----------------
__device__ __forceinline__ void split_h(float x, __half& hi, __half& lo) {
    hi = __float2half_rn(x);
    lo = __float2half_rn(x - __half2float(hi));
}

// ---------------- init: index dtype detection + degree zero ----------------
__global__ void k_init(const void* srcp) {
    int n = blockIdx.x * blockDim.x + threadIdx.x;
    if (n < NN) g_deg[n] = 0;
    if (blockIdx.x == 0 && threadIdx.x < 32) {
        const long long* s = (const long long*)srcp;
        long long v = s[threadIdx.x];
        int ok = (v >= 0 && v < NN) ? 1 : 0;
        ok = __all_sync(~0u, ok);
        if (threadIdx.x == 0) g_idx64 = ok;
    }
}

// features (fp32) -> hi/lo fp16
__global__ void k_cvt_f(const float2* __restrict__ f) {
    int i = blockIdx.x * blockDim.x + threadIdx.x;
    if (i >= NN * 32) return;
    float2 v = f[i];
    __half h0, l0, h1, l1;
    split_h(v.x, h0, l0);
    split_h(v.y, h1, l1);
    *(__half2*)&g_fh[(size_t)i * 2] = __halves2half2(h0, h1);
    *(__half2*)&g_fl[(size_t)i * 2] = __halves2half2(l0, l1);
}

// all weights: split + transpose into [col][k] arena
__global__ void k_prep_all(const float* __restrict__ Ws1, const float* __restrict__ Wn1,
                           const float* __restrict__ Ws2, const float* __restrict__ Wn2,
                           const float* __restrict__ Wm1, const float* __restrict__ Wm2) {
    int i = blockIdx.x * blockDim.x + threadIdx.x;
    if (i >= 73728) return;
    float v;
    if (i < 16384) {                       // L1: K=128, K0=64, NCOL=128
        int col = i / 128, k = i % 128;
        v = (k < 64) ? Ws1[k * 128 + col] : Wn1[(k - 64) * 128 + col];
    } else if (i < 49152) {                // L2: K=256, K0=128, NCOL=128
        int j = i - 16384;
        int col = j / 256, k = j % 256;
        v = (k < 128) ? Ws2[k * 128 + col] : Wn2[(k - 128) * 128 + col];
    } else if (i < 65536) {                // L3: K=128, NCOL=128
        int j = i - 49152;
        int col = j / 128, k = j % 128;
        v = Wm1[k * 128 + col];
    } else {                               // L4: K=128, NCOL=64
        int j = i - 65536;
        int col = j / 128, k = j % 128;
        v = Wm2[k * 64 + col];
    }
    __half h, l;
    split_h(v, h, l);
    g_wh[i] = h;
    g_wl[i] = l;
}

__device__ __forceinline__ int load_idx(const void* p, int e) {
    return g_idx64 ? (int)((const long long*)p)[e] : ((const int*)p)[e];
}

// ---------------- CSR build: count, 3-phase scan, fill ----------------
__global__ void k_count(const void* dstp) {
    int e = blockIdx.x * blockDim.x + threadIdx.x;
    if (e >= EE) return;
    atomicAdd(&g_deg[load_idx(dstp, e)], 1);
}

__global__ __launch_bounds__(1024) void k_scan1() {
    __shared__ int ws[32];
    int t = threadIdx.x, lane = t & 31, wid = t >> 5;
    int idx = blockIdx.x * 1024 + t;
    int s = (idx < NN) ? g_deg[idx] : 0;
#pragma unroll
    for (int o = 16; o > 0; o >>= 1) s += __shfl_down_sync(~0u, s, o);
    if (lane == 0) ws[wid] = s;
    __syncthreads();
    if (wid == 0) {
        int x = ws[lane];
#pragma unroll
        for (int o = 16; o > 0; o >>= 1) x += __shfl_down_sync(~0u, x, o);
        if (lane == 0) g_blocksum[blockIdx.x] = x;
    }
}

__global__ __launch_bounds__(128) void k_scan2(int nb) {
    __shared__ int ws[4];
    int t = threadIdx.x, lane = t & 31, wid = t >> 5;
    int v = (t < nb) ? g_blocksum[t] : 0;
    int inc = v;
#pragma unroll
    for (int o = 1; o < 32; o <<= 1) {
        int n = __shfl_up_sync(~0u, inc, o);
        if (lane >= o) inc += n;
    }
    if (lane == 31) ws[wid] = inc;
    __syncthreads();
    int add = 0;
    for (int i = 0; i < wid; i++) add += ws[i];
    if (t < nb) g_blockoff[t] = inc - v + add;  // exclusive
}

__global__ __launch_bounds__(1024) void k_scan3() {
    __shared__ int ws[32];
    int t = threadIdx.x, lane = t & 31, wid = t >> 5;
    int idx = blockIdx.x * 1024 + t;
    int v = (idx < NN) ? g_deg[idx] : 0;
    int inc = v;
#pragma unroll
    for (int o = 1; o < 32; o <<= 1) {
        int n = __shfl_up_sync(~0u, inc, o);
        if (lane >= o) inc += n;
    }
    if (lane == 31) ws[wid] = inc;
    __syncthreads();
    if (wid == 0) {
        int x = ws[lane];
#pragma unroll
        for (int o = 1; o < 32; o <<= 1) {
            int n = __shfl_up_sync(~0u, x, o);
            if (lane >= o) x += n;
        }
        ws[lane] = x;
    }
    __syncthreads();
    int exc = inc - v + (wid > 0 ? ws[wid - 1] : 0) + g_blockoff[blockIdx.x];
    if (idx < NN) {
        g_rowstart[idx] = exc;
        g_cur[idx] = exc;
    }
    if (idx == NN - 1) g_rowstart[NN] = EE;
}

__global__ void k_fill(const void* srcp, const void* dstp) {
    int e = blockIdx.x * blockDim.x + threadIdx.x;
    if (e >= EE) return;
    int s = load_idx(srcp, e);
    int d = load_idx(dstp, e);
    int pos = atomicAdd(&g_cur[d], 1);
    g_adj[pos] = s;
}

// ---------------- fp16 gather aggregation -> hi/lo split output ----------
template <int LANES>
__global__ void k_gather_h(const uint4* __restrict__ x,
                           __half* __restrict__ hh, __half* __restrict__ hl) {
    int tid = blockIdx.x * blockDim.x + threadIdx.x;
    int node = tid / LANES;
    int l = tid % LANES;
    if (node >= NN) return;
    int i = g_rowstart[node];
    const int end = g_rowstart[node + 1];
    const int deg = end - i;
    float acc[8];
#pragma unroll
    for (int j = 0; j < 8; j++) acc[j] = 0.f;
#pragma unroll 1
    for (; i + 4 <= end; i += 4) {
        int n0 = g_adj[i], n1 = g_adj[i + 1], n2 = g_adj[i + 2], n3 = g_adj[i + 3];
        uint4 v0 = x[(size_t)n0 * LANES + l];
        uint4 v1 = x[(size_t)n1 * LANES + l];
        uint4 v2 = x[(size_t)n2 * LANES + l];
        uint4 v3 = x[(size_t)n3 * LANES + l];
        const uint32_t* vs[4] = {&v0.x, &v1.x, &v2.x, &v3.x};
#pragma unroll
        for (int q = 0; q < 4; q++) {
#pragma unroll
            for (int j = 0; j < 4; j++) {
                float2 f = __half22float2(*(const __half2*)&vs[q][j]);
                acc[2 * j] += f.x;
                acc[2 * j + 1] += f.y;
            }
        }
    }
    for (; i < end; i++) {
        uint4 v = x[(size_t)g_adj[i] * LANES + l];
        const uint32_t* vp = &v.x;
#pragma unroll
        for (int j = 0; j < 4; j++) {
            float2 f = __half22float2(*(const __half2*)&vp[j]);
            acc[2 * j] += f.x;
            acc[2 * j + 1] += f.y;
        }
    }
    float inv = 1.f / (float)max(deg, 1);
    __half hv[8], lv[8];
#pragma unroll
    for (int j = 0; j < 8; j++) split_h(acc[j] * inv, hv[j], lv[j]);
    size_t o = ((size_t)node * LANES + l) * 8;
    *(uint4*)&hh[o] = *(uint4*)hv;
    *(uint4*)&hl[o] = *(uint4*)lv;
}

// ---------------- FP16x2-split tensor-core fused dense layer ----------------
// All operands pre-split hi/lo fp16 in global memory: staging is pure uint4
// copies; inner loop is pure LDS+HMMA (3-term: ah*bh + ah*bl + al*bh).
// Tile: 128 rows x NCOL cols, 256 threads, 2 CTAs/SM.

__device__ __forceinline__ void mma_fp16(float c[4], uint32_t a0, uint32_t a1,
                                         uint32_t a2, uint32_t a3,
                                         uint32_t b0, uint32_t b1) {
    asm volatile(
        "mma.sync.aligned.m16n8k16.row.col.f32.f16.f16.f32 "
        "{%0,%1,%2,%3}, {%4,%5,%6,%7}, {%8,%9}, {%0,%1,%2,%3};"
        : "+f"(c[0]), "+f"(c[1]), "+f"(c[2]), "+f"(c[3])
        : "r"(a0), "r"(a1), "r"(a2), "r"(a3), "r"(b0), "r"(b1));
}

#define HSTR 40  // fragment LDS bank = (4g+t) mod 32, all lanes distinct

template <int K, int K0, int NCOL, bool RELU, bool WH, bool WF>
__global__ __launch_bounds__(256, 2) void k_gemm_fp16s(
    const __half* __restrict__ Ah0, const __half* __restrict__ Al0,
    const __half* __restrict__ Ah1, const __half* __restrict__ Al1,
    const __half* __restrict__ Bh, const __half* __restrict__ Bl,
    const float* __restrict__ bias, float* __restrict__ out,
    __half* __restrict__ outh, __half* __restrict__ outl) {
    constexpr int MT = (NCOL == 128) ? 2 : 1;
    constexpr int NT = 8;
    constexpr int NTG = 4;

    __shared__ __half As_hi[128 * HSTR];
    __shared__ __half As_lo[128 * HSTR];
    __shared__ __half Bs_hi[NCOL * HSTR];   // [col][k]
    __shared__ __half Bs_lo[NCOL * HSTR];

    const int tid = threadIdx.x;
    const int w = tid >> 5;
    const int lane = tid & 31;
    const int g = lane >> 2;
    const int t = lane & 3;
    const int rowBase = blockIdx.x * 128;

    const int rbase = (NCOL == 128) ? (w & 3) * 32 : w * 16;
    const int cbase = (NCOL == 128) ? (w >> 2) * 64 : 0;

    float acc[MT][NT][4];
#pragma unroll
    for (int mt = 0; mt < MT; mt++)
#pragma unroll
        for (int nt = 0; nt < NT; nt++)
#pragma unroll
            for (int i = 0; i < 4; i++) acc[mt][nt][i] = 0.f;

    // A prefetch: per 32-k chunk, 2 hi + 2 lo uint4 per thread
    const int pr0 = tid >> 2, pq0 = tid & 3;
    const int pr1 = (tid + 256) >> 2, pq1 = tid & 3;
    uint4 pah[2], pal[2];
    auto loadA = [&](int kc) {
        const __half *sAh, *sAl;
        int stride;
        if (kc < K0) { sAh = Ah0; sAl = Al0; stride = K0; }
        else { sAh = Ah1; sAl = Al1; stride = K - K0; kc -= K0; }
        int gr0 = rowBase + pr0, gr1 = rowBase + pr1;
        pah[0] = pal[0] = pah[1] = pal[1] = make_uint4(0, 0, 0, 0);
        if (gr0 < NN) {
            pah[0] = *(const uint4*)(sAh + (size_t)gr0 * stride + kc + pq0 * 8);
            pal[0] = *(const uint4*)(sAl + (size_t)gr0 * stride + kc + pq0 * 8);
        }
        if (gr1 < NN) {
            pah[1] = *(const uint4*)(sAh + (size_t)gr1 * stride + kc + pq1 * 8);
            pal[1] = *(const uint4*)(sAl + (size_t)gr1 * stride + kc + pq1 * 8);
        }
    };

    loadA(0);
    for (int kc = 0; kc < K; kc += 32) {
        // stage A from prefetch regs
        *(uint4*)&As_hi[pr0 * HSTR + pq0 * 8] = pah[0];
        *(uint4*)&As_lo[pr0 * HSTR + pq0 * 8] = pal[0];
        *(uint4*)&As_hi[pr1 * HSTR + pq1 * 8] = pah[1];
        *(uint4*)&As_lo[pr1 * HSTR + pq1 * 8] = pal[1];
        // stage B: NCOL cols x 4 uint4 (32 halves = full K-chunk) per array
#pragma unroll
        for (int x = tid; x < NCOL * 4; x += 256) {
            int c = x >> 2, q = x & 3;
            *(uint4*)&Bs_hi[c * HSTR + q * 8] =
                *(const uint4*)(Bh + (size_t)c * K + kc + q * 8);
            *(uint4*)&Bs_lo[c * HSTR + q * 8] =
                *(const uint4*)(Bl + (size_t)c * K + kc + q * 8);
        }
        __syncthreads();

        if (kc + 32 < K) loadA(kc + 32);  // latency overlaps MMA below

#pragma unroll
        for (int k16 = 0; k16 < 2; k16++) {
            const int kk = k16 * 16;
            uint32_t ah[MT][4], al[MT][4];
#pragma unroll
            for (int mt = 0; mt < MT; mt++) {
                int r0 = rbase + mt * 16 + g;
                const __half* ph = As_hi + kk + 2 * t;
                const __half* pl = As_lo + kk + 2 * t;
                ah[mt][0] = *(const uint32_t*)(ph + r0 * HSTR);
                ah[mt][1] = *(const uint32_t*)(ph + (r0 + 8) * HSTR);
                ah[mt][2] = *(const uint32_t*)(ph + r0 * HSTR + 8);
                ah[mt][3] = *(const uint32_t*)(ph + (r0 + 8) * HSTR + 8);
                al[mt][0] = *(const uint32_t*)(pl + r0 * HSTR);
                al[mt][1] = *(const uint32_t*)(pl + (r0 + 8) * HSTR);
                al[mt][2] = *(const uint32_t*)(pl + r0 * HSTR + 8);
                al[mt][3] = *(const uint32_t*)(pl + (r0 + 8) * HSTR + 8);
            }
#pragma unroll
            for (int ng = 0; ng < NT / NTG; ng++) {
                uint32_t bh[NTG][2], bl[NTG][2];
#pragma unroll
                for (int j = 0; j < NTG; j++) {
                    int col = cbase + (ng * NTG + j) * 8 + g;
                    const __half* ph = Bs_hi + col * HSTR + kk + 2 * t;
                    const __half* pl = Bs_lo + col * HSTR + kk + 2 * t;
                    bh[j][0] = *(const uint32_t*)(ph);
                    bh[j][1] = *(const uint32_t*)(ph + 8);
                    bl[j][0] = *(const uint32_t*)(pl);
                    bl[j][1] = *(const uint32_t*)(pl + 8);
                }
#pragma unroll
                for (int mt = 0; mt < MT; mt++) {
#pragma unroll
                    for (int j = 0; j < NTG; j++) {
                        float* a = acc[mt][ng * NTG + j];
                        mma_fp16(a, ah[mt][0], ah[mt][1], ah[mt][2], ah[mt][3],
                                 bh[j][0], bh[j][1]);
                        mma_fp16(a, ah[mt][0], ah[mt][1], ah[mt][2], ah[mt][3],
                                 bl[j][0], bl[j][1]);
                        mma_fp16(a, al[mt][0], al[mt][1], al[mt][2], al[mt][3],
                                 bh[j][0], bh[j][1]);
                    }
                }
            }
        }
        __syncthreads();
    }

    // epilogue: bias + optional relu; write hi/lo fp16 and/or fp32
#pragma unroll
    for (int mt = 0; mt < MT; mt++) {
#pragma unroll
        for (int nt = 0; nt < NT; nt++) {
            int col = cbase + nt * 8 + t * 2;
            float b0 = bias[col], b1 = bias[col + 1];
#pragma unroll
            for (int half = 0; half < 2; half++) {
                int gr = rowBase + rbase + mt * 16 + g + half * 8;
                if (gr < NN) {
                    float v0 = acc[mt][nt][half * 2 + 0] + b0;
                    float v1 = acc[mt][nt][half * 2 + 1] + b1;
                    if (RELU) { v0 = fmaxf(v0, 0.f); v1 = fmaxf(v1, 0.f); }
                    if (WF)
                        *(float2*)(out + (size_t)gr * NCOL + col) =
                            make_float2(v0, v1);
                    if (WH) {
                        __half h0, l0, h1, l1;
                        split_h(v0, h0, l0);
                        split_h(v1, h1, l1);
                        *(__half2*)(outh + (size_t)gr * NCOL + col) =
                            __halves2half2(h0, h1);
                        *(__half2*)(outl + (size_t)gr * NCOL + col) =
                            __halves2half2(l0, l1);
                    }
                }
            }
        }
    }
}

// ---------------- launch ----------------
extern "C" void kernel_launch(void* const* d_in, const int* in_sizes, int n_in,
                              void* d_out, int out_size) {
    const float* features = (const float*)d_in[0];
    const float* Wn1 = (const float*)d_in[1];
    const float* Ws1 = (const float*)d_in[2];
    const float* b1  = (const float*)d_in[3];
    const float* Wn2 = (const float*)d_in[4];
    const float* Ws2 = (const float*)d_in[5];
    const float* b2  = (const float*)d_in[6];
    const float* Wm1 = (const float*)d_in[7];
    const float* bm1 = (const float*)d_in[8];
    const float* Wm2 = (const float*)d_in[9];
    const float* bm2 = (const float*)d_in[10];
    const void*  src = d_in[11];
    const void*  dst = d_in[12];
    float* out = (float*)d_out;

    __half *p_fh, *p_fl, *p_h1h, *p_h1l, *p_x1h, *p_x1l;
    __half *p_h2h, *p_h2l, *p_x2h, *p_x2l, *p_x3h, *p_x3l, *p_wh, *p_wl;
    cudaGetSymbolAddress((void**)&p_fh, g_fh);
    cudaGetSymbolAddress((void**)&p_fl, g_fl);
    cudaGetSymbolAddress((void**)&p_h1h, g_h1h);
    cudaGetSymbolAddress((void**)&p_h1l, g_h1l);
    cudaGetSymbolAddress((void**)&p_x1h, g_x1h);
    cudaGetSymbolAddress((void**)&p_x1l, g_x1l);
    cudaGetSymbolAddress((void**)&p_h2h, g_h2h);
    cudaGetSymbolAddress((void**)&p_h2l, g_h2l);
    cudaGetSymbolAddress((void**)&p_x2h, g_x2h);
    cudaGetSymbolAddress((void**)&p_x2l, g_x2l);
    cudaGetSymbolAddress((void**)&p_x3h, g_x3h);
    cudaGetSymbolAddress((void**)&p_x3l, g_x3l);
    cudaGetSymbolAddress((void**)&p_wh, g_wh);
    cudaGetSymbolAddress((void**)&p_wl, g_wl);

    const int GEMM_BLOCKS = (NN + 127) / 128;  // 782
    const int EB = (EE + 255) / 256;
    const int NB = (NN + 1023) / 1024;

    // CSR build first (ncu -s 5 -c 1 lands on k_fill)
    k_init<<<(NN + 255) / 256, 256>>>(src);
    k_count<<<EB, 256>>>(dst);
    k_scan1<<<NB, 1024>>>();
    k_scan2<<<1, 128>>>(NB);
    k_scan3<<<NB, 1024>>>();
    k_fill<<<EB, 256>>>(src, dst);

    // operand prep
    k_cvt_f<<<(NN * 32 + 255) / 256, 256>>>((const float2*)features);
    k_prep_all<<<(73728 + 255) / 256, 256>>>(Ws1, Wn1, Ws2, Wn2, Wm1, Wm2);

    // layer 1
    k_gather_h<8><<<(NN * 8 + 255) / 256, 256>>>((const uint4*)p_fh, p_h1h, p_h1l);
    k_gemm_fp16s<128, 64, 128, true, true, false><<<GEMM_BLOCKS, 256>>>(
        p_fh, p_fl, p_h1h, p_h1l, p_wh, p_wl, b1, nullptr, p_x1h, p_x1l);

    // layer 2
    k_gather_h<16><<<(NN * 16 + 255) / 256, 256>>>((const uint4*)p_x1h, p_h2h, p_h2l);
    k_gemm_fp16s<256, 128, 128, true, true, false><<<GEMM_BLOCKS, 256>>>(
        p_x1h, p_x1l, p_h2h, p_h2l, p_wh + 16384, p_wl + 16384, b2,
        nullptr, p_x2h, p_x2l);

    // MLP head (separate kernels — fusion regressed in R12 via register spill)
    k_gemm_fp16s<128, 128, 128, true, true, false><<<GEMM_BLOCKS, 256>>>(
        p_x2h, p_x2l, p_x2h, p_x2l, p_wh + 49152, p_wl + 49152, bm1,
        nullptr, p_x3h, p_x3l);
    k_gemm_fp16s<128, 128, 64, false, false, true><<<GEMM_BLOCKS, 256>>>(
        p_x3h, p_x3l, p_x3h, p_x3l, p_wh + 65536, p_wl + 65536, bm2,
        out, nullptr, nullptr);
}

// round 16
// speedup vs baseline: 1.1464x; 1.0629x over previous
#include <cuda_runtime.h>
#include <cuda_fp16.h>
#include <stdint.h>

#define NN 100000
#define EE 1600000
// dims: IN=64, HID=128, OUT=64

// ---------------- device scratch (no allocation allowed) ----------------
__device__ int g_idx64;
__device__ __align__(16) int    g_deg[NN];
__device__ __align__(16) int    g_rowstart[NN + 1];
__device__ __align__(16) int    g_cur[NN];
__device__ __align__(16) int    g_adj[EE];
__device__ __align__(16) int    g_blocksum[128];
__device__ __align__(16) int    g_blockoff[128];
// GEMM operands pre-split to fp16 hi/lo
__device__ __align__(16) __half g_fh [(size_t)NN * 64];
__device__ __align__(16) __half g_fl [(size_t)NN * 64];
__device__ __align__(16) __half g_h1h[(size_t)NN * 64];
__device__ __align__(16) __half g_h1l[(size_t)NN * 64];
__device__ __align__(16) __half g_x1h[(size_t)NN * 128];
__device__ __align__(16) __half g_x1l[(size_t)NN * 128];
__device__ __align__(16) __half g_h2h[(size_t)NN * 128];
__device__ __align__(16) __half g_h2l[(size_t)NN * 128];
__device__ __align__(16) __half g_x2h[(size_t)NN * 128];
__device__ __align__(16) __half g_x2l[(size_t)NN * 128];
__device__ __align__(16) __half g_x3h[(size_t)NN * 128];
__device__ __align__(16) __half g_x3l[(size_t)NN * 128];
// weight arenas, pre-split + pre-transposed to [col][k]
// offsets: L1=0 (128x128), L2=16384 (256x128), L3=49152 (128x128), L4=65536 (128x64)
__device__ __align__(16) __half g_wh[73728];
__device__ __align__(16) __half g_wl[73728];

// ---------------- small helpers ----------------
__device__ __forceinline__ void split_h(float x, __half& hi, __half& lo) {
    hi = __float2half_rn(x);
    lo = __float2half_rn(x - __half2float(hi));
}

// ---------------- init: index dtype detection + degree zero ----------------
__global__ void k_init(const void* srcp) {
    int n = blockIdx.x * blockDim.x + threadIdx.x;
    if (n < NN) g_deg[n] = 0;
    if (blockIdx.x == 0 && threadIdx.x < 32) {
        const long long* s = (const long long*)srcp;
        long long v = s[threadIdx.x];
        int ok = (v >= 0 && v < NN) ? 1 : 0;
        ok = __all_sync(~0u, ok);
        if (threadIdx.x == 0) g_idx64 = ok;
    }
}

// features (fp32) -> hi/lo fp16
__global__ void k_cvt_f(const float2* __restrict__ f) {
    int i = blockIdx.x * blockDim.x + threadIdx.x;
    if (i >= NN * 32) return;
    float2 v = f[i];
    __half h0, l0, h1, l1;
    split_h(v.x, h0, l0);
    split_h(v.y, h1, l1);
    *(__half2*)&g_fh[(size_t)i * 2] = __halves2half2(h0, h1);
    *(__half2*)&g_fl[(size_t)i * 2] = __halves2half2(l0, l1);
}

// all weights: split + transpose into [col][k] arena
__global__ void k_prep_all(const float* __restrict__ Ws1, const float* __restrict__ Wn1,
                           const float* __restrict__ Ws2, const float* __restrict__ Wn2,
                           const float* __restrict__ Wm1, const float* __restrict__ Wm2) {
    int i = blockIdx.x * blockDim.x + threadIdx.x;
    if (i >= 73728) return;
    float v;
    if (i < 16384) {                       // L1: K=128, K0=64, NCOL=128
        int col = i / 128, k = i % 128;
        v = (k < 64) ? Ws1[k * 128 + col] : Wn1[(k - 64) * 128 + col];
    } else if (i < 49152) {                // L2: K=256, K0=128, NCOL=128
        int j = i - 16384;
        int col = j / 256, k = j % 256;
        v = (k < 128) ? Ws2[k * 128 + col] : Wn2[(k - 128) * 128 + col];
    } else if (i < 65536) {                // L3: K=128, NCOL=128
        int j = i - 49152;
        int col = j / 128, k = j % 128;
        v = Wm1[k * 128 + col];
    } else {                               // L4: K=128, NCOL=64
        int j = i - 65536;
        int col = j / 128, k = j % 128;
        v = Wm2[k * 64 + col];
    }
    __half h, l;
    split_h(v, h, l);
    g_wh[i] = h;
    g_wl[i] = l;
}

__device__ __forceinline__ int load_idx(const void* p, int e) {
    return g_idx64 ? (int)((const long long*)p)[e] : ((const int*)p)[e];
}

// ---------------- CSR build: count, 3-phase scan, fill ----------------
__global__ void k_count(const void* dstp) {
    int e = blockIdx.x * blockDim.x + threadIdx.x;
    if (e >= EE) return;
    atomicAdd(&g_deg[load_idx(dstp, e)], 1);
}

__global__ __launch_bounds__(1024) void k_scan1() {
    __shared__ int ws[32];
    int t = threadIdx.x, lane = t & 31, wid = t >> 5;
    int idx = blockIdx.x * 1024 + t;
    int s = (idx < NN) ? g_deg[idx] : 0;
#pragma unroll
    for (int o = 16; o > 0; o >>= 1) s += __shfl_down_sync(~0u, s, o);
    if (lane == 0) ws[wid] = s;
    __syncthreads();
    if (wid == 0) {
        int x = ws[lane];
#pragma unroll
        for (int o = 16; o > 0; o >>= 1) x += __shfl_down_sync(~0u, x, o);
        if (lane == 0) g_blocksum[blockIdx.x] = x;
    }
}

__global__ __launch_bounds__(128) void k_scan2(int nb) {
    __shared__ int ws[4];
    int t = threadIdx.x, lane = t & 31, wid = t >> 5;
    int v = (t < nb) ? g_blocksum[t] : 0;
    int inc = v;
#pragma unroll
    for (int o = 1; o < 32; o <<= 1) {
        int n = __shfl_up_sync(~0u, inc, o);
        if (lane >= o) inc += n;
    }
    if (lane == 31) ws[wid] = inc;
    __syncthreads();
    int add = 0;
    for (int i = 0; i < wid; i++) add += ws[i];
    if (t < nb) g_blockoff[t] = inc - v + add;  // exclusive
}

__global__ __launch_bounds__(1024) void k_scan3() {
    __shared__ int ws[32];
    int t = threadIdx.x, lane = t & 31, wid = t >> 5;
    int idx = blockIdx.x * 1024 + t;
    int v = (idx < NN) ? g_deg[idx] : 0;
    int inc = v;
#pragma unroll
    for (int o = 1; o < 32; o <<= 1) {
        int n = __shfl_up_sync(~0u, inc, o);
        if (lane >= o) inc += n;
    }
    if (lane == 31) ws[wid] = inc;
    __syncthreads();
    if (wid == 0) {
        int x = ws[lane];
#pragma unroll
        for (int o = 1; o < 32; o <<= 1) {
            int n = __shfl_up_sync(~0u, x, o);
            if (lane >= o) x += n;
        }
        ws[lane] = x;
    }
    __syncthreads();
    int exc = inc - v + (wid > 0 ? ws[wid - 1] : 0) + g_blockoff[blockIdx.x];
    if (idx < NN) {
        g_rowstart[idx] = exc;
        g_cur[idx] = exc;
    }
    if (idx == NN - 1) g_rowstart[NN] = EE;
}

__global__ void k_fill(const void* srcp, const void* dstp) {
    int e = blockIdx.x * blockDim.x + threadIdx.x;
    if (e >= EE) return;
    int s = load_idx(srcp, e);
    int d = load_idx(dstp, e);
    int pos = atomicAdd(&g_cur[d], 1);
    g_adj[pos] = s;
}

// ---------------- fp16 gather aggregation -> hi/lo split output ----------
template <int LANES>
__global__ void k_gather_h(const uint4* __restrict__ x,
                           __half* __restrict__ hh, __half* __restrict__ hl) {
    int tid = blockIdx.x * blockDim.x + threadIdx.x;
    int node = tid / LANES;
    int l = tid % LANES;
    if (node >= NN) return;
    int i = g_rowstart[node];
    const int end = g_rowstart[node + 1];
    const int deg = end - i;
    float acc[8];
#pragma unroll
    for (int j = 0; j < 8; j++) acc[j] = 0.f;
#pragma unroll 1
    for (; i + 4 <= end; i += 4) {
        int n0 = g_adj[i], n1 = g_adj[i + 1], n2 = g_adj[i + 2], n3 = g_adj[i + 3];
        uint4 v0 = x[(size_t)n0 * LANES + l];
        uint4 v1 = x[(size_t)n1 * LANES + l];
        uint4 v2 = x[(size_t)n2 * LANES + l];
        uint4 v3 = x[(size_t)n3 * LANES + l];
        const uint32_t* vs[4] = {&v0.x, &v1.x, &v2.x, &v3.x};
#pragma unroll
        for (int q = 0; q < 4; q++) {
#pragma unroll
            for (int j = 0; j < 4; j++) {
                float2 f = __half22float2(*(const __half2*)&vs[q][j]);
                acc[2 * j] += f.x;
                acc[2 * j + 1] += f.y;
            }
        }
    }
    for (; i < end; i++) {
        uint4 v = x[(size_t)g_adj[i] * LANES + l];
        const uint32_t* vp = &v.x;
#pragma unroll
        for (int j = 0; j < 4; j++) {
            float2 f = __half22float2(*(const __half2*)&vp[j]);
            acc[2 * j] += f.x;
            acc[2 * j + 1] += f.y;
        }
    }
    float inv = 1.f / (float)max(deg, 1);
    __half hv[8], lv[8];
#pragma unroll
    for (int j = 0; j < 8; j++) split_h(acc[j] * inv, hv[j], lv[j]);
    size_t o = ((size_t)node * LANES + l) * 8;
    *(uint4*)&hh[o] = *(uint4*)hv;
    *(uint4*)&hl[o] = *(uint4*)lv;
}

// ---------------- FP16x2-split tensor-core fused dense layer ----------------
// Pre-split hi/lo operands; fragments loaded via ldmatrix (24 LDSM/chunk/warp
// replacing 96 scalar LDS). 3-term MMA: ah*bh + ah*bl + al*bh.
// Tile: 128 rows x NCOL cols, 256 threads, 2 CTAs/SM.

__device__ __forceinline__ void mma_fp16(float c[4], uint32_t a0, uint32_t a1,
                                         uint32_t a2, uint32_t a3,
                                         uint32_t b0, uint32_t b1) {
    asm volatile(
        "mma.sync.aligned.m16n8k16.row.col.f32.f16.f16.f32 "
        "{%0,%1,%2,%3}, {%4,%5,%6,%7}, {%8,%9}, {%0,%1,%2,%3};"
        : "+f"(c[0]), "+f"(c[1]), "+f"(c[2]), "+f"(c[3])
        : "r"(a0), "r"(a1), "r"(a2), "r"(a3), "r"(b0), "r"(b1));
}

#define LDSM_X4(r, addr) \
    asm volatile("ldmatrix.sync.aligned.m8n8.x4.shared.b16 {%0,%1,%2,%3}, [%4];" \
                 : "=r"((r)[0]), "=r"((r)[1]), "=r"((r)[2]), "=r"((r)[3]) \
                 : "r"(addr))

#define HSTR 40  // 80B row stride: LDSM phases hit all 32 banks exactly once

template <int K, int K0, int NCOL, bool RELU, bool WH, bool WF>
__global__ __launch_bounds__(256, 2) void k_gemm_fp16s(
    const __half* __restrict__ Ah0, const __half* __restrict__ Al0,
    const __half* __restrict__ Ah1, const __half* __restrict__ Al1,
    const __half* __restrict__ Bh, const __half* __restrict__ Bl,
    const float* __restrict__ bias, float* __restrict__ out,
    __half* __restrict__ outh, __half* __restrict__ outl) {
    constexpr int MT = (NCOL == 128) ? 2 : 1;
    constexpr int NT = 8;

    __shared__ __half As_hi[128 * HSTR];
    __shared__ __half As_lo[128 * HSTR];
    __shared__ __half Bs_hi[NCOL * HSTR];   // [col][k]
    __shared__ __half Bs_lo[NCOL * HSTR];

    const int tid = threadIdx.x;
    const int w = tid >> 5;
    const int lane = tid & 31;
    const int g = lane >> 2;
    const int t = lane & 3;
    const int rowBase = blockIdx.x * 128;

    const int rbase = (NCOL == 128) ? (w & 3) * 32 : w * 16;
    const int cbase = (NCOL == 128) ? (w >> 2) * 64 : 0;

    float acc[MT][NT][4];
#pragma unroll
    for (int mt = 0; mt < MT; mt++)
#pragma unroll
        for (int nt = 0; nt < NT; nt++)
#pragma unroll
            for (int i = 0; i < 4; i++) acc[mt][nt][i] = 0.f;

    // ldmatrix per-lane base addresses (half-index * 2 = bytes)
    // A x4: m = rbase + (lane&15) [+16*mt], k = kk + (lane>>4)*8
    const uint32_t aIdx = (uint32_t)((rbase + (lane & 15)) * HSTR + (lane >> 4) * 8);
    const uint32_t aBh = (uint32_t)__cvta_generic_to_shared(As_hi) + aIdx * 2;
    const uint32_t aBl = (uint32_t)__cvta_generic_to_shared(As_lo) + aIdx * 2;
    // B x4 (2 nt tiles per load): n = n0 + (lane&7) + ((lane>>4)&1)*8,
    //                             k = kk + ((lane>>3)&1)*8; n0 = cbase + p*16
    const uint32_t bIdx = (uint32_t)((cbase + (lane & 7) + ((lane >> 4) & 1) * 8) * HSTR
                                     + ((lane >> 3) & 1) * 8);
    const uint32_t bBh = (uint32_t)__cvta_generic_to_shared(Bs_hi) + bIdx * 2;
    const uint32_t bBl = (uint32_t)__cvta_generic_to_shared(Bs_lo) + bIdx * 2;

    // A prefetch: per 32-k chunk, 2 hi + 2 lo uint4 per thread
    const int pr0 = tid >> 2, pq0 = tid & 3;
    const int pr1 = (tid + 256) >> 2, pq1 = tid & 3;
    uint4 pah[2], pal[2];
    auto loadA = [&](int kc) {
        const __half *sAh, *sAl;
        int stride;
        if (kc < K0) { sAh = Ah0; sAl = Al0; stride = K0; }
        else { sAh = Ah1; sAl = Al1; stride = K - K0; kc -= K0; }
        int gr0 = rowBase + pr0, gr1 = rowBase + pr1;
        pah[0] = pal[0] = pah[1] = pal[1] = make_uint4(0, 0, 0, 0);
        if (gr0 < NN) {
            pah[0] = *(const uint4*)(sAh + (size_t)gr0 * stride + kc + pq0 * 8);
            pal[0] = *(const uint4*)(sAl + (size_t)gr0 * stride + kc + pq0 * 8);
        }
        if (gr1 < NN) {
            pah[1] = *(const uint4*)(sAh + (size_t)gr1 * stride + kc + pq1 * 8);
            pal[1] = *(const uint4*)(sAl + (size_t)gr1 * stride + kc + pq1 * 8);
        }
    };

    loadA(0);
    for (int kc = 0; kc < K; kc += 32) {
        // stage A from prefetch regs
        *(uint4*)&As_hi[pr0 * HSTR + pq0 * 8] = pah[0];
        *(uint4*)&As_lo[pr0 * HSTR + pq0 * 8] = pal[0];
        *(uint4*)&As_hi[pr1 * HSTR + pq1 * 8] = pah[1];
        *(uint4*)&As_lo[pr1 * HSTR + pq1 * 8] = pal[1];
        // stage B: NCOL cols x 4 uint4 (32 halves = full K-chunk) per array
#pragma unroll
        for (int x = tid; x < NCOL * 4; x += 256) {
            int c = x >> 2, q = x & 3;
            *(uint4*)&Bs_hi[c * HSTR + q * 8] =
                *(const uint4*)(Bh + (size_t)c * K + kc + q * 8);
            *(uint4*)&Bs_lo[c * HSTR + q * 8] =
                *(const uint4*)(Bl + (size_t)c * K + kc + q * 8);
        }
        __syncthreads();

        if (kc + 32 < K) loadA(kc + 32);  // latency overlaps MMA below

#pragma unroll
        for (int k16 = 0; k16 < 2; k16++) {
            const uint32_t kkB = (uint32_t)(k16 * 16 * 2);  // kk bytes
            uint32_t ah[MT][4], al[MT][4];
#pragma unroll
            for (int mt = 0; mt < MT; mt++) {
                LDSM_X4(ah[mt], aBh + (uint32_t)(mt * 16 * HSTR * 2) + kkB);
                LDSM_X4(al[mt], aBl + (uint32_t)(mt * 16 * HSTR * 2) + kkB);
            }
#pragma unroll
            for (int p = 0; p < 4; p++) {  // pair p covers nt tiles 2p, 2p+1
                uint32_t bh[4], bl[4];
                LDSM_X4(bh, bBh + (uint32_t)(p * 16 * HSTR * 2) + kkB);
                LDSM_X4(bl, bBl + (uint32_t)(p * 16 * HSTR * 2) + kkB);
#pragma unroll
                for (int mt = 0; mt < MT; mt++) {
#pragma unroll
                    for (int s = 0; s < 2; s++) {
                        float* a = acc[mt][2 * p + s];
                        mma_fp16(a, ah[mt][0], ah[mt][1], ah[mt][2], ah[mt][3],
                                 bh[2 * s], bh[2 * s + 1]);
                        mma_fp16(a, ah[mt][0], ah[mt][1], ah[mt][2], ah[mt][3],
                                 bl[2 * s], bl[2 * s + 1]);
                        mma_fp16(a, al[mt][0], al[mt][1], al[mt][2], al[mt][3],
                                 bh[2 * s], bh[2 * s + 1]);
                    }
                }
            }
        }
        __syncthreads();
    }

    // epilogue: bias + optional relu; write hi/lo fp16 and/or fp32
#pragma unroll
    for (int mt = 0; mt < MT; mt++) {
#pragma unroll
        for (int nt = 0; nt < NT; nt++) {
            int col = cbase + nt * 8 + t * 2;
            float b0 = bias[col], b1 = bias[col + 1];
#pragma unroll
            for (int half = 0; half < 2; half++) {
                int gr = rowBase + rbase + mt * 16 + g + half * 8;
                if (gr < NN) {
                    float v0 = acc[mt][nt][half * 2 + 0] + b0;
                    float v1 = acc[mt][nt][half * 2 + 1] + b1;
                    if (RELU) { v0 = fmaxf(v0, 0.f); v1 = fmaxf(v1, 0.f); }
                    if (WF)
                        *(float2*)(out + (size_t)gr * NCOL + col) =
                            make_float2(v0, v1);
                    if (WH) {
                        __half h0, l0, h1, l1;
                        split_h(v0, h0, l0);
                        split_h(v1, h1, l1);
                        *(__half2*)(outh + (size_t)gr * NCOL + col) =
                            __halves2half2(h0, h1);
                        *(__half2*)(outl + (size_t)gr * NCOL + col) =
                            __halves2half2(l0, l1);
                    }
                }
            }
        }
    }
}

// ---------------- launch ----------------
extern "C" void kernel_launch(void* const* d_in, const int* in_sizes, int n_in,
                              void* d_out, int out_size) {
    const float* features = (const float*)d_in[0];
    const float* Wn1 = (const float*)d_in[1];
    const float* Ws1 = (const float*)d_in[2];
    const float* b1  = (const float*)d_in[3];
    const float* Wn2 = (const float*)d_in[4];
    const float* Ws2 = (const float*)d_in[5];
    const float* b2  = (const float*)d_in[6];
    const float* Wm1 = (const float*)d_in[7];
    const float* bm1 = (const float*)d_in[8];
    const float* Wm2 = (const float*)d_in[9];
    const float* bm2 = (const float*)d_in[10];
    const void*  src = d_in[11];
    const void*  dst = d_in[12];
    float* out = (float*)d_out;

    __half *p_fh, *p_fl, *p_h1h, *p_h1l, *p_x1h, *p_x1l;
    __half *p_h2h, *p_h2l, *p_x2h, *p_x2l, *p_x3h, *p_x3l, *p_wh, *p_wl;
    cudaGetSymbolAddress((void**)&p_fh, g_fh);
    cudaGetSymbolAddress((void**)&p_fl, g_fl);
    cudaGetSymbolAddress((void**)&p_h1h, g_h1h);
    cudaGetSymbolAddress((void**)&p_h1l, g_h1l);
    cudaGetSymbolAddress((void**)&p_x1h, g_x1h);
    cudaGetSymbolAddress((void**)&p_x1l, g_x1l);
    cudaGetSymbolAddress((void**)&p_h2h, g_h2h);
    cudaGetSymbolAddress((void**)&p_h2l, g_h2l);
    cudaGetSymbolAddress((void**)&p_x2h, g_x2h);
    cudaGetSymbolAddress((void**)&p_x2l, g_x2l);
    cudaGetSymbolAddress((void**)&p_x3h, g_x3h);
    cudaGetSymbolAddress((void**)&p_x3l, g_x3l);
    cudaGetSymbolAddress((void**)&p_wh, g_wh);
    cudaGetSymbolAddress((void**)&p_wl, g_wl);

    const int GEMM_BLOCKS = (NN + 127) / 128;  // 782
    const int EB = (EE + 255) / 256;
    const int NB = (NN + 1023) / 1024;

    // CSR build first
    k_init<<<(NN + 255) / 256, 256>>>(src);
    k_count<<<EB, 256>>>(dst);
    k_scan1<<<NB, 1024>>>();
    k_scan2<<<1, 128>>>(NB);
    k_scan3<<<NB, 1024>>>();
    k_fill<<<EB, 256>>>(src, dst);

    // operand prep
    k_cvt_f<<<(NN * 32 + 255) / 256, 256>>>((const float2*)features);
    k_prep_all<<<(73728 + 255) / 256, 256>>>(Ws1, Wn1, Ws2, Wn2, Wm1, Wm2);

    // layer 1
    k_gather_h<8><<<(NN * 8 + 255) / 256, 256>>>((const uint4*)p_fh, p_h1h, p_h1l);
    k_gemm_fp16s<128, 64, 128, true, true, false><<<GEMM_BLOCKS, 256>>>(
        p_fh, p_fl, p_h1h, p_h1l, p_wh, p_wl, b1, nullptr, p_x1h, p_x1l);

    // layer 2
    k_gather_h<16><<<(NN * 16 + 255) / 256, 256>>>((const uint4*)p_x1h, p_h2h, p_h2l);
    k_gemm_fp16s<256, 128, 128, true, true, false><<<GEMM_BLOCKS, 256>>>(
        p_x1h, p_x1l, p_h2h, p_h2l, p_wh + 16384, p_wl + 16384, b2,
        nullptr, p_x2h, p_x2l);

    // MLP head (separate kernels — fusion regressed in R12 via register spill)
    k_gemm_fp16s<128, 128, 128, true, true, false><<<GEMM_BLOCKS, 256>>>(
        p_x2h, p_x2l, p_x2h, p_x2l, p_wh + 49152, p_wl + 49152, bm1,
        nullptr, p_x3h, p_x3l);
    k_gemm_fp16s<128, 128, 64, false, false, true><<<GEMM_BLOCKS, 256>>>(
        p_x3h, p_x3l, p_x3h, p_x3l, p_wh + 65536, p_wl + 65536, bm2,
        out, nullptr, nullptr);
}